// round 16
// baseline (speedup 1.0000x reference)
#include <cuda_runtime.h>
#include <cuda_bf16.h>
#include <mma.h>
#include <cstdint>

using namespace nvcuda;

#define NP 8
#define HD 1024
#define BD 2048
#define BN 128
#define BM1 64           // gemm1 CTA rows
#define BM2 128          // gemm2 CTA rows
#define APITCH 40        // gemm1 A pitch: 32+8 elems
#define BPITCH 136       // B pitch: 128+8 elems
#define AP2 72           // gemm2 A pitch: 64+8 elems
#define BK1 32
#define BK2 64
#define NT1 32           // 1024/32 (full K, no split)
#define NT2 16           // 1024/64

// ---------------- device scratch ----------------
__device__ float g_v[NP];    // (1-alpha)*u[j]
__device__ float g_cw[NP];   // alpha*u[j]

__device__ __nv_bfloat16 g_Wi_hi[HD * HD];   // A1 (bf16)
__device__ __nv_bfloat16 g_We_hi[HD * HD];   // B1 (bf16)
__device__ __nv_bfloat16 g_M_hi[HD * HD];    // B2 (written by gemm1 epilogue)
__device__ __nv_bfloat16 g_x_hi[BD * HD];    // A2
__device__ float g_cr[BD * HD];              // coherent reduction

// ---------------- kernel 1: scalars ----------------
__global__ void prep_kernel(const float* __restrict__ J, const float* __restrict__ t_ptr) {
    if (threadIdx.x != 0) return;
    const float t = t_ptr[0];
    float alpha = expf(-t / 51.0f);
    alpha = fminf(fmaxf(alpha, 0.0f), 1.0f);
    const float phase = 2.0f * 3.14159265358979323846f * 20.0f * t / 1000.0f;
    float colsum[NP];
#pragma unroll
    for (int j = 0; j < NP; j++) colsum[j] = 0.0f;
    for (int i = 0; i < NP; i++) {
        float row[NP];
        float mx = -1e30f;
#pragma unroll
        for (int j = 0; j < NP; j++) {
            float js = 0.5f * (J[i * NP + j] + J[j * NP + i]);
            row[j] = cosf(phase * js);
            mx = fmaxf(mx, row[j]);
        }
        float s = 0.0f;
#pragma unroll
        for (int j = 0; j < NP; j++) { row[j] = expf(row[j] - mx); s += row[j]; }
        float inv_s = 1.0f / s;
#pragma unroll
        for (int j = 0; j < NP; j++) colsum[j] += row[j] * inv_s;
    }
    const float scale = alpha / (float)(NP * NP);
#pragma unroll
    for (int j = 0; j < NP; j++) {
        float u = scale * colsum[j];
        g_v[j]  = (1.0f - alpha) * u;
        g_cw[j] = alpha * u;
    }
}

// ---------------- kernel 2: W_eff build + W_input -> bf16 ----------------
__global__ void build_weff_kernel(const float* __restrict__ Wp, const float* __restrict__ Wi) {
    const int e = (blockIdx.x * blockDim.x + threadIdx.x) * 4;
    float4 s = make_float4(0.f, 0.f, 0.f, 0.f);
#pragma unroll
    for (int j = 0; j < NP; j++) {
        const float4 w = *(const float4*)&Wp[(size_t)j * (HD * HD) + e];
        const float v = g_v[j];
        s.x = fmaf(v, w.x, s.x); s.y = fmaf(v, w.y, s.y);
        s.z = fmaf(v, w.z, s.z); s.w = fmaf(v, w.w, s.w);
    }
    __nv_bfloat16 hi[4];
    hi[0] = __float2bfloat16(s.x); hi[1] = __float2bfloat16(s.y);
    hi[2] = __float2bfloat16(s.z); hi[3] = __float2bfloat16(s.w);
    *(uint2*)&g_We_hi[e] = *(uint2*)hi;

    const float4 w = *(const float4*)&Wi[e];
    hi[0] = __float2bfloat16(w.x); hi[1] = __float2bfloat16(w.y);
    hi[2] = __float2bfloat16(w.z); hi[3] = __float2bfloat16(w.w);
    *(uint2*)&g_Wi_hi[e] = *(uint2*)hi;
}

// ---------------- kernel 3: fused x->bf16 + coherent reduction (side stream) ----------------
__global__ void ew_kernel(const float* __restrict__ x, const float* __restrict__ coh) {
    const int idx = blockIdx.x * blockDim.x + threadIdx.x;
    const int e = idx * 4;
    const int b = e >> 10;
    const int h = e & 1023;

    const float4 v4 = *(const float4*)&x[e];
    __nv_bfloat16 hi[4];
    hi[0] = __float2bfloat16(v4.x);
    hi[1] = __float2bfloat16(v4.y);
    hi[2] = __float2bfloat16(v4.z);
    hi[3] = __float2bfloat16(v4.w);
    *(uint2*)&g_x_hi[e] = *(uint2*)hi;

    float4 acc = make_float4(0.f, 0.f, 0.f, 0.f);
#pragma unroll
    for (int j = 0; j < NP; j++) {
        const float4 c = *(const float4*)&coh[((size_t)b * NP + j) * HD + h];
        const float w = g_cw[j];
        acc.x = fmaf(w, c.x, acc.x);
        acc.y = fmaf(w, c.y, acc.y);
        acc.z = fmaf(w, c.z, acc.z);
        acc.w = fmaf(w, c.w, acc.w);
    }
    *(float4*)&g_cr[e] = acc;
}

// ---------------- cp.async helper ----------------
__device__ __forceinline__ void cp16(void* s, const void* g) {
    unsigned sa = (unsigned)__cvta_generic_to_shared(s);
    asm volatile("cp.async.cg.shared.global [%0], [%1], 16;\n" :: "r"(sa), "l"(g));
}
#define CP_COMMIT() asm volatile("cp.async.commit_group;\n")
#define CP_WAIT1()  asm volatile("cp.async.wait_group 1;\n")
#define CP_WAIT0()  asm volatile("cp.async.wait_group 0;\n")

// ---------------- GEMM1: single-pass bf16, CTA 64x128, full K, bf16 epilogue ----------------
// 128 thr = 4 warps (2m x 2n); warp tile 32x64 = 2x4 wmma. Writes g_M_hi directly.
__global__ void __launch_bounds__(128) gemm1_kernel() {
    constexpr int A_ONE = BM1 * APITCH * 2;       // 5120
    constexpr int B_ONE = BK1 * BPITCH * 2;       // 8704
    constexpr int OFF_B = A_ONE;
    constexpr int STAGE = A_ONE + B_ONE;          // 13824

    extern __shared__ __align__(16) unsigned char smem[];

    const int tid    = threadIdx.x;
    const int wid    = tid >> 5;
    const int lane   = tid & 31;
    const int warp_m = wid & 1;        // 32-row strip
    const int warp_n = wid >> 1;       // 64-col strip
    const int mBase  = blockIdx.y * BM1;
    const int nBase  = blockIdx.x * BN;

    auto load_stage = [&](int s, int kt) {
        const int k0 = kt * BK1;
        unsigned char* st = smem + s * STAGE;
        // A: 64 rows x 32 cols = 256 x 16B chunks -> 2/thread
#pragma unroll
        for (int i = 0; i < 2; i++) {
            const int c   = tid + i * 128;
            const int row = c >> 2;
            const int ch  = c & 3;
            cp16(st + row * (APITCH * 2) + ch * 16,
                 g_Wi_hi + (size_t)(mBase + row) * HD + k0 + ch * 8);
        }
        // B: 32 rows x 128 cols = 512 x 16B chunks -> 4/thread
#pragma unroll
        for (int i = 0; i < 4; i++) {
            const int c   = tid + i * 128;
            const int row = c >> 4;
            const int ch  = c & 15;
            cp16(st + OFF_B + row * (BPITCH * 2) + ch * 16,
                 g_We_hi + (size_t)(k0 + row) * HD + nBase + ch * 8);
        }
        CP_COMMIT();
    };

    wmma::fragment<wmma::accumulator, 16, 16, 16, float> acc[2][4];
#pragma unroll
    for (int mi = 0; mi < 2; mi++)
#pragma unroll
        for (int ni = 0; ni < 4; ni++) wmma::fill_fragment(acc[mi][ni], 0.0f);

    load_stage(0, 0);
    load_stage(1, 1);

    for (int it = 0; it < NT1; ++it) {
        if (it + 1 < NT1) CP_WAIT1(); else CP_WAIT0();
        __syncthreads();
        if (it + 2 < NT1) load_stage((it + 2) % 3, it + 2);

        const unsigned char* st = smem + (it % 3) * STAGE;
        const __nv_bfloat16* pA = (const __nv_bfloat16*)(st);
        const __nv_bfloat16* pB = (const __nv_bfloat16*)(st + OFF_B);

#pragma unroll
        for (int kc = 0; kc < 2; kc++) {
            wmma::fragment<wmma::matrix_a, 16, 16, 16, __nv_bfloat16, wmma::row_major> fa[2];
            wmma::fragment<wmma::matrix_b, 16, 16, 16, __nv_bfloat16, wmma::row_major> fb[4];
#pragma unroll
            for (int mi = 0; mi < 2; mi++)
                wmma::load_matrix_sync(fa[mi], pA + (warp_m * 32 + mi * 16) * APITCH + kc * 16, APITCH);
#pragma unroll
            for (int ni = 0; ni < 4; ni++)
                wmma::load_matrix_sync(fb[ni], pB + (kc * 16) * BPITCH + warp_n * 64 + ni * 16, BPITCH);
#pragma unroll
            for (int mi = 0; mi < 2; mi++)
#pragma unroll
                for (int ni = 0; ni < 4; ni++)
                    wmma::mma_sync(acc[mi][ni], fa[mi], fb[ni], acc[mi][ni]);
        }
    }

    // epilogue: stage via smem, convert to bf16, write g_M_hi directly
    __syncthreads();
    float* buf = (float*)smem + wid * 1024;   // 16x64 f32 per warp
#pragma unroll
    for (int mi = 0; mi < 2; mi++) {
#pragma unroll
        for (int ni = 0; ni < 4; ni++)
            wmma::store_matrix_sync(buf + ni * 16, acc[mi][ni], 64, wmma::mem_row_major);
        __syncwarp();
#pragma unroll
        for (int p = 0; p < 8; p++) {
            const int idx = p * 128 + lane * 4;
            const int r   = idx >> 6;
            const int c   = idx & 63;
            const float4 v = *(float4*)&buf[r * 64 + c];
            __nv_bfloat16 hv[4];
            hv[0] = __float2bfloat16(v.x);
            hv[1] = __float2bfloat16(v.y);
            hv[2] = __float2bfloat16(v.z);
            hv[3] = __float2bfloat16(v.w);
            const size_t ob = (size_t)(mBase + warp_m * 32 + mi * 16 + r) * HD
                            + nBase + warp_n * 64 + c;
            *(uint2*)&g_M_hi[ob] = *(uint2*)hv;
        }
        __syncwarp();
    }
}

// ---------------- GEMM2: single-pass bf16, tile 128x128, 4 warps (64x64/warp), BK=64 ----
__global__ void __launch_bounds__(128) gemm2_kernel(float* __restrict__ Cf) {
    constexpr int A_ONE = BM2 * AP2 * 2;       // 18432
    constexpr int B_ONE = BK2 * BPITCH * 2;    // 17408
    constexpr int OFF_B = A_ONE;
    constexpr int STAGE = A_ONE + B_ONE;       // 35840

    extern __shared__ __align__(16) unsigned char smem[];

    const int tid    = threadIdx.x;
    const int wid    = tid >> 5;
    const int lane   = tid & 31;
    const int warp_m = wid & 1;
    const int warp_n = wid >> 1;
    const int mBase  = blockIdx.y * BM2;
    const int nBase  = blockIdx.x * BN;

    auto load_stage = [&](int s, int kt) {
        const int k0 = kt * BK2;
        unsigned char* st = smem + s * STAGE;
        // A: 128 rows x 64 cols = 1024 x 16B -> 8/thread
#pragma unroll
        for (int i = 0; i < 8; i++) {
            const int c   = tid + i * 128;
            const int row = c >> 3;
            const int ch  = c & 7;
            cp16(st + row * (AP2 * 2) + ch * 16,
                 g_x_hi + (size_t)(mBase + row) * HD + k0 + ch * 8);
        }
        // B: 64 rows x 128 cols = 1024 x 16B -> 8/thread
#pragma unroll
        for (int i = 0; i < 8; i++) {
            const int c   = tid + i * 128;
            const int row = c >> 4;
            const int ch  = c & 15;
            cp16(st + OFF_B + row * (BPITCH * 2) + ch * 16,
                 g_M_hi + (size_t)(k0 + row) * HD + nBase + ch * 8);
        }
        CP_COMMIT();
    };

    wmma::fragment<wmma::accumulator, 16, 16, 16, float> acc[4][4];
#pragma unroll
    for (int mi = 0; mi < 4; mi++)
#pragma unroll
        for (int ni = 0; ni < 4; ni++) wmma::fill_fragment(acc[mi][ni], 0.0f);

    load_stage(0, 0);
    load_stage(1, 1);

    for (int it = 0; it < NT2; ++it) {
        if (it + 1 < NT2) CP_WAIT1(); else CP_WAIT0();
        __syncthreads();
        if (it + 2 < NT2) load_stage((it + 2) % 3, it + 2);

        const unsigned char* st = smem + (it % 3) * STAGE;
        const __nv_bfloat16* pA = (const __nv_bfloat16*)(st);
        const __nv_bfloat16* pB = (const __nv_bfloat16*)(st + OFF_B);

#pragma unroll
        for (int kc = 0; kc < 4; kc++) {
            wmma::fragment<wmma::matrix_a, 16, 16, 16, __nv_bfloat16, wmma::row_major> fa[4];
            wmma::fragment<wmma::matrix_b, 16, 16, 16, __nv_bfloat16, wmma::row_major> fb[4];
#pragma unroll
            for (int mi = 0; mi < 4; mi++)
                wmma::load_matrix_sync(fa[mi], pA + (warp_m * 64 + mi * 16) * AP2 + kc * 16, AP2);
#pragma unroll
            for (int ni = 0; ni < 4; ni++)
                wmma::load_matrix_sync(fb[ni], pB + (kc * 16) * BPITCH + warp_n * 64 + ni * 16, BPITCH);
#pragma unroll
            for (int mi = 0; mi < 4; mi++)
#pragma unroll
                for (int ni = 0; ni < 4; ni++)
                    wmma::mma_sync(acc[mi][ni], fa[mi], fb[ni], acc[mi][ni]);
        }
    }

    // epilogue: stage 16x64 per warp via smem, add g_cr, float4 store
    __syncthreads();
    float* buf = (float*)smem + wid * 1024;
#pragma unroll
    for (int mi = 0; mi < 4; mi++) {
#pragma unroll
        for (int ni = 0; ni < 4; ni++)
            wmma::store_matrix_sync(buf + ni * 16, acc[mi][ni], 64, wmma::mem_row_major);
        __syncwarp();
#pragma unroll
        for (int p = 0; p < 8; p++) {
            const int idx = p * 128 + lane * 4;
            const int r   = idx >> 6;
            const int c   = idx & 63;
            float4 v = *(float4*)&buf[r * 64 + c];
            const int b   = mBase + warp_m * 64 + mi * 16 + r;
            const int col = nBase + warp_n * 64 + c;
            const float4 cr = *(const float4*)&g_cr[(size_t)b * HD + col];
            v.x += cr.x; v.y += cr.y; v.z += cr.z; v.w += cr.w;
            *(float4*)&Cf[(size_t)b * HD + col] = v;
        }
        __syncwarp();
    }
}

#define SMB1 (3 * (BM1 * APITCH * 2 + BK1 * BPITCH * 2))   // 41472
#define SMB2 (3 * (BM2 * AP2 * 2 + BK2 * BPITCH * 2))      // 107520

// ---------------- launch: fork-join overlap of ew with build_weff+gemm1 ----------------
static cudaStream_t s_aux = nullptr;
static cudaEvent_t  ev_fork = nullptr, ev_join = nullptr;

extern "C" void kernel_launch(void* const* d_in, const int* in_sizes, int n_in,
                              void* d_out, int out_size) {
    (void)in_sizes; (void)n_in; (void)out_size;
    const float* x   = (const float*)d_in[0];
    const float* Wi  = (const float*)d_in[1];
    const float* Wp  = (const float*)d_in[2];
    const float* J   = (const float*)d_in[3];
    const float* coh = (const float*)d_in[4];
    const float* t   = (const float*)d_in[5];
    float* out = (float*)d_out;

    if (s_aux == nullptr) {   // host-side objects, created once on the (uncaptured) correctness call
        cudaStreamCreateWithFlags(&s_aux, cudaStreamNonBlocking);
        cudaEventCreateWithFlags(&ev_fork, cudaEventDisableTiming);
        cudaEventCreateWithFlags(&ev_join, cudaEventDisableTiming);
    }

    cudaFuncSetAttribute(gemm1_kernel, cudaFuncAttributeMaxDynamicSharedMemorySize, SMB1);
    cudaFuncSetAttribute(gemm2_kernel, cudaFuncAttributeMaxDynamicSharedMemorySize, SMB2);

    prep_kernel<<<1, 32>>>(J, t);

    // fork: ew (DRAM-bound) runs concurrently with build_weff+gemm1 (dispatch-bound)
    cudaEventRecord(ev_fork, 0);
    cudaStreamWaitEvent(s_aux, ev_fork, 0);
    ew_kernel<<<(BD * HD / 4) / 256, 256, 0, s_aux>>>(x, coh);

    build_weff_kernel<<<(HD * HD / 4) / 256, 256>>>(Wp, Wi);
    {   // GEMM1: CTA 64x128, grid 8 x 16 = 128 CTAs, writes g_M_hi directly
        dim3 g(HD / BN, HD / BM1);
        gemm1_kernel<<<g, 128, SMB1>>>();
    }

    // join
    cudaEventRecord(ev_join, s_aux);
    cudaStreamWaitEvent(0, ev_join, 0);

    {   // GEMM2: grid 8 x 16 = 128 CTAs
        dim3 g(HD / BN, BD / BM2);
        gemm2_kernel<<<g, 128, SMB2>>>(out);
    }
}